// round 11
// baseline (speedup 1.0000x reference)
#include <cuda_runtime.h>
#include <cuda_fp16.h>
#include <math.h>
#include <stdint.h>

// Problem dims
constexpr int kB  = 4;
constexpr int kT  = 2048;
constexpr int kD  = 1024;
constexpr int kH  = 16;
constexpr int kDH = 64;
constexpr int kBT = kB * kT;           // 8192
constexpr int kQKVN = 3 * kD;          // 3072

// Scratch
__device__ float  g_qkv[(size_t)kBT * kQKVN];      // 96 MB (gemm1 out, fp32)
__device__ __half g_xh[(size_t)kBT * kD];          // x in fp16
__device__ __half g_wqkvt[(size_t)kQKVN * kD];     // Wqkv^T fp16 [3072][1024]
__device__ __half g_woutt[(size_t)kD * kD];        // Wout^T fp16
__device__ __half g_qh[(size_t)kBT * kD];          // [bh][t][64], scaled 1/8
__device__ __half g_kh[(size_t)kBT * kD];
__device__ __half g_vh[(size_t)kBT * kD];          // [bh][t][64]
__device__ __half g_vt[(size_t)kBT * kD];          // [bh][64][kT] (V transposed)
__device__ __half g_atth[(size_t)kBT * kD];        // [bt][h*64+d]

// ---------------------------------------------------------------------------
__device__ __forceinline__ uint32_t packh2(float a, float b) {
    __half2 h = __floats2half2_rn(a, b);
    return *reinterpret_cast<uint32_t*>(&h);
}
__device__ __forceinline__ uint32_t smem_u32(const void* p) {
    return (uint32_t)__cvta_generic_to_shared(p);
}

__device__ __forceinline__ void mma16(float& d0, float& d1, float& d2, float& d3,
                                      uint32_t a0, uint32_t a1, uint32_t a2, uint32_t a3,
                                      uint32_t b0, uint32_t b1) {
    asm volatile(
        "mma.sync.aligned.m16n8k16.row.col.f32.f16.f16.f32 "
        "{%0,%1,%2,%3}, {%4,%5,%6,%7}, {%8,%9}, {%0,%1,%2,%3};\n"
        : "+f"(d0), "+f"(d1), "+f"(d2), "+f"(d3)
        : "r"(a0), "r"(a1), "r"(a2), "r"(a3), "r"(b0), "r"(b1));
}

__device__ __forceinline__ void ldsm4(uint32_t& r0, uint32_t& r1, uint32_t& r2,
                                      uint32_t& r3, uint32_t a) {
    asm volatile("ldmatrix.sync.aligned.m8n8.x4.shared.b16 {%0,%1,%2,%3}, [%4];"
        : "=r"(r0), "=r"(r1), "=r"(r2), "=r"(r3) : "r"(a));
}

__device__ __forceinline__ void cpa16(void* s, const void* g) {
    uint32_t sa = (uint32_t)__cvta_generic_to_shared(s);
    asm volatile("cp.async.cg.shared.global [%0], [%1], 16;\n" :: "r"(sa), "l"(g));
}
__device__ __forceinline__ void cpa_commit() {
    asm volatile("cp.async.commit_group;\n");
}

// ---------------------------------------------------------------------------
__global__ __launch_bounds__(256)
void round_half_kernel(const float* __restrict__ in, __half2* __restrict__ out, int n4)
{
    int i = blockIdx.x * blockDim.x + threadIdx.x;
    if (i >= n4) return;
    float4 v = ((const float4*)in)[i];
    out[2 * i]     = __floats2half2_rn(v.x, v.y);
    out[2 * i + 1] = __floats2half2_rn(v.z, v.w);
}

// W [K][N] float -> W^T [N][K] fp16
__global__ __launch_bounds__(256)
void round_transpose_kernel(const float* __restrict__ in, __half* __restrict__ out,
                            int K, int N)
{
    __shared__ float tile[32][33];
    int k0 = blockIdx.y * 32, n0 = blockIdx.x * 32;
    int tx = threadIdx.x & 31, ty = threadIdx.x >> 5;   // 32 x 8
    #pragma unroll
    for (int r = 0; r < 32; r += 8)
        tile[ty + r][tx] = in[(size_t)(k0 + ty + r) * N + n0 + tx];
    __syncthreads();
    #pragma unroll
    for (int r = 0; r < 32; r += 8)
        out[(size_t)(n0 + ty + r) * K + k0 + tx] = __float2half_rn(tile[tx][ty + r]);
}

// ---------------------------------------------------------------------------
// fp16 GEMM, ldmatrix frags, BK=64 (4 k16-slices per sync). CTA 128x128,
// 8 warps (2x4), warp tile 64x32, 3-stage cp.async pipeline.
// smem: 3 x (A[128][72] + B[128][72]) halves = 110,592 B -> 2 CTAs/SM.
// ---------------------------------------------------------------------------
constexpr int GH_TILE_H = 128 * 72;                    // 9216 halves
constexpr int GH_STAGE_H = 2 * GH_TILE_H;              // 18432
constexpr int GH_SMEM_BYTES = 3 * GH_STAGE_H * 2;      // 110592

__global__ __launch_bounds__(256, 2)
void gemm_h_kernel(const __half* __restrict__ A, const __half* __restrict__ Bt,
                   float* __restrict__ C, int M, int N, int K)
{
    extern __shared__ __half smh[];

    const int tid  = threadIdx.x;
    const int lane = tid & 31, warp = tid >> 5;
    const int wm = (warp >> 2) * 64, wn = (warp & 3) * 32;
    const int g = lane >> 2, tg = lane & 3;
    const int brow = blockIdx.y * 128, bcol = blockIdx.x * 128;

    // ldmatrix per-lane row/k offsets (row stride 72 halves)
    const int rowA = wm + (lane & 15);
    const int kA   = (lane >> 4) << 3;
    const int rowB = wn + (lane & 7) + ((lane >> 4) << 3);
    const int kBo  = ((lane >> 3) & 1) << 3;

    const uint32_t smbase = smem_u32(smh);
    const uint32_t aOff = (uint32_t)(rowA * 72 + kA) * 2;
    const uint32_t bOff = (uint32_t)GH_TILE_H * 2 + (uint32_t)(rowB * 72 + kBo) * 2;

    float acc[4][4][4];
    #pragma unroll
    for (int a = 0; a < 4; a++)
        #pragma unroll
        for (int b = 0; b < 4; b++)
            #pragma unroll
            for (int c = 0; c < 4; c++) acc[a][b][c] = 0.f;

    const int iters = K >> 6;   // BK = 64

    auto load_stage = [&](int s, int k0) {
        __half* As = smh + s * GH_STAGE_H;
        __half* Bs = As + GH_TILE_H;
        #pragma unroll
        for (int u = 0; u < 4; u++) {          // A: 128 rows x 8 cp16
            int idx = tid + u * 256;
            int r = idx >> 3, c16 = idx & 7;
            cpa16(As + r * 72 + c16 * 8, A + (size_t)(brow + r) * K + k0 + c16 * 8);
        }
        #pragma unroll
        for (int u = 0; u < 4; u++) {          // B: 128 n-rows x 8 cp16
            int idx = tid + u * 256;
            int r = idx >> 3, c16 = idx & 7;
            cpa16(Bs + r * 72 + c16 * 8, Bt + (size_t)(bcol + r) * K + k0 + c16 * 8);
        }
    };

    load_stage(0, 0);  cpa_commit();
    load_stage(1, 64); cpa_commit();

    for (int it = 0; it < iters; it++) {
        if (it + 1 < iters) asm volatile("cp.async.wait_group 1;\n");
        else                asm volatile("cp.async.wait_group 0;\n");
        __syncthreads();
        if (it + 2 < iters) {
            load_stage((it + 2) % 3, (it + 2) << 6);
            cpa_commit();
        }
        const uint32_t stg = smbase + (uint32_t)((it % 3) * GH_STAGE_H) * 2;
        const uint32_t aAddr = stg + aOff;
        const uint32_t bAddr = stg + bOff;

        #pragma unroll
        for (int ks = 0; ks < 64; ks += 16) {
            uint32_t a[4][4], bq[2][4];
            #pragma unroll
            for (int mt = 0; mt < 4; mt++)
                ldsm4(a[mt][0], a[mt][1], a[mt][2], a[mt][3],
                      aAddr + (uint32_t)(mt * 16 * 72 + ks) * 2);
            #pragma unroll
            for (int np = 0; np < 2; np++)
                ldsm4(bq[np][0], bq[np][1], bq[np][2], bq[np][3],
                      bAddr + (uint32_t)(np * 16 * 72 + ks) * 2);
            #pragma unroll
            for (int nt = 0; nt < 4; nt++) {
                uint32_t b0 = bq[nt >> 1][(nt & 1) * 2];
                uint32_t b1 = bq[nt >> 1][(nt & 1) * 2 + 1];
                #pragma unroll
                for (int mt = 0; mt < 4; mt++)
                    mma16(acc[mt][nt][0], acc[mt][nt][1], acc[mt][nt][2], acc[mt][nt][3],
                          a[mt][0], a[mt][1], a[mt][2], a[mt][3], b0, b1);
            }
        }
    }

    #pragma unroll
    for (int mt = 0; mt < 4; mt++) {
        #pragma unroll
        for (int nt = 0; nt < 4; nt++) {
            int r0 = brow + wm + mt * 16 + g;
            int c0 = bcol + wn + nt * 8 + 2 * tg;
            *(float2*)&C[(size_t)r0 * N + c0]       = make_float2(acc[mt][nt][0], acc[mt][nt][1]);
            *(float2*)&C[(size_t)(r0 + 8) * N + c0] = make_float2(acc[mt][nt][2], acc[mt][nt][3]);
        }
    }
}

// ---------------------------------------------------------------------------
// RoPE + split/transpose; outputs fp16; folds 1/8 softmax scale into Q.
// ---------------------------------------------------------------------------
__global__ __launch_bounds__(256)
void rope_kernel()
{
    int idx = blockIdx.x * blockDim.x + threadIdx.x;
    if (idx >= kBT * kH * 32) return;
    int i  = idx & 31;
    int h  = (idx >> 5) & (kH - 1);
    int bt = idx >> 9;
    int t  = bt & (kT - 1);
    int b  = bt >> 11;

    float inv_freq = expf(-((float)(2 * i) / 64.0f) * 9.210340371976184f);
    float ang = (float)t * inv_freq;
    float s, c;
    sincosf(ang, &s, &c);

    size_t src = (size_t)bt * kQKVN + h * kDH + i;
    float q1 = g_qkv[src],        q2 = g_qkv[src + 32];
    float k1 = g_qkv[src + 1024], k2 = g_qkv[src + 1056];
    float v1 = g_qkv[src + 2048], v2 = g_qkv[src + 2080];

    size_t dst = ((size_t)(b * kH + h) * kT + t) * kDH + i;
    g_qh[dst]      = __float2half_rn(0.125f * (q1 * c - q2 * s));
    g_qh[dst + 32] = __float2half_rn(0.125f * (q2 * c + q1 * s));
    g_kh[dst]      = __float2half_rn(k1 * c - k2 * s);
    g_kh[dst + 32] = __float2half_rn(k2 * c + k1 * s);
    g_vh[dst]      = __float2half_rn(v1);
    g_vh[dst + 32] = __float2half_rn(v2);
}

// V [bh][t][64] -> Vt [bh][64][kT]
__global__ __launch_bounds__(256)
void vtrans_kernel()
{
    __shared__ uint16_t tl[64][66];
    int t0 = blockIdx.x * 64;
    int bh = blockIdx.y;
    const uint32_t* src = (const uint32_t*)(g_vh + ((size_t)bh * kT + t0) * 64);
    #pragma unroll
    for (int it = 0; it < 8; it++) {
        int idx = threadIdx.x + it * 256;
        int r = idx >> 5, c2 = idx & 31;
        uint32_t v = src[r * 32 + c2];
        tl[r][2 * c2]     = (uint16_t)(v & 0xFFFF);
        tl[r][2 * c2 + 1] = (uint16_t)(v >> 16);
    }
    __syncthreads();
    #pragma unroll
    for (int it = 0; it < 8; it++) {
        int idx = threadIdx.x + it * 256;
        int d = idx >> 5, c2 = idx & 31;
        int t = 2 * c2;
        uint32_t v = (uint32_t)tl[t][d] | ((uint32_t)tl[t + 1][d] << 16);
        *(uint32_t*)(g_vt + ((size_t)(bh * 64 + d)) * kT + t0 + t) = v;
    }
}

// ---------------------------------------------------------------------------
// Flash attention, fp16 mma, register Q/P, ldmatrix K/V frags.
// smem: K + V^T tiles double-buffered: 2 x 2 x 64 x 72 halves = 36,864 B.
// ---------------------------------------------------------------------------
constexpr int ATT_TILE_H = 64 * 72;
constexpr int ATT_STAGE_H = 2 * ATT_TILE_H;
constexpr int ATT_SMEM_BYTES = 2 * ATT_STAGE_H * 2;    // 36864

__global__ __launch_bounds__(128)
void attn_h_kernel()
{
    extern __shared__ __half smh[];

    const int qt = blockIdx.x;
    const int bh = blockIdx.y;
    const int b  = bh >> 4, h = bh & 15;
    const int tid = threadIdx.x, lane = tid & 31, warp = tid >> 5;
    const int g = lane >> 2, tg = lane & 3;
    const int m0 = warp * 32;

    const __half* Qg = g_qh + ((size_t)bh * kT + qt * 128) * kDH;
    const __half* Kg = g_kh + (size_t)bh * kT * kDH;
    const __half* Vt = g_vt + (size_t)bh * 64 * kT;

    const int rowL = (lane & 7) + ((lane >> 4) << 3);
    const int kL   = ((lane >> 3) & 1) << 3;
    const uint32_t smbase = smem_u32(smh);
    const uint32_t lOff = (uint32_t)(rowL * 72 + kL) * 2;

    // Q fragments in registers
    uint32_t qf[4][2][4];
    #pragma unroll
    for (int kk = 0; kk < 4; kk++)
        #pragma unroll
        for (int mt = 0; mt < 2; mt++) {
            int r0 = m0 + mt * 16 + g;
            int k = kk * 16 + 2 * tg;
            qf[kk][mt][0] = *(const uint32_t*)(Qg + (size_t)r0 * 64 + k);
            qf[kk][mt][1] = *(const uint32_t*)(Qg + (size_t)(r0 + 8) * 64 + k);
            qf[kk][mt][2] = *(const uint32_t*)(Qg + (size_t)r0 * 64 + k + 8);
            qf[kk][mt][3] = *(const uint32_t*)(Qg + (size_t)(r0 + 8) * 64 + k + 8);
        }

    float o[2][8][4];
    #pragma unroll
    for (int mt = 0; mt < 2; mt++)
        #pragma unroll
        for (int nt = 0; nt < 8; nt++)
            #pragma unroll
            for (int e = 0; e < 4; e++) o[mt][nt][e] = 0.f;
    float mrow[4] = {-1e30f, -1e30f, -1e30f, -1e30f};
    float lrow[4] = {0.f, 0.f, 0.f, 0.f};

    const int nkt = 2 * qt + 2;

    auto load_stage = [&](int s, int kt) {
        __half* sK = smh + s * ATT_STAGE_H;
        __half* sV = sK + ATT_TILE_H;
        int bt0 = kt * 64;
        #pragma unroll
        for (int u = 0; u < 4; u++) {
            int idx = tid + u * 128;
            int r = idx >> 3, c16 = idx & 7;
            cpa16(sK + r * 72 + c16 * 8, Kg + ((size_t)(bt0 + r)) * 64 + c16 * 8);
        }
        #pragma unroll
        for (int u = 0; u < 4; u++) {
            int idx = tid + u * 128;
            int r = idx >> 3, c16 = idx & 7;
            cpa16(sV + r * 72 + c16 * 8, Vt + (size_t)r * kT + bt0 + c16 * 8);
        }
    };

    load_stage(0, 0);
    cpa_commit();

    for (int kt = 0; kt < nkt; kt++) {
        __syncthreads();
        if (kt + 1 < nkt) {
            load_stage((kt + 1) & 1, kt + 1);
            cpa_commit();
            asm volatile("cp.async.wait_group 1;\n");
        } else {
            asm volatile("cp.async.wait_group 0;\n");
        }
        __syncthreads();
        const uint32_t kAddr = smbase + (uint32_t)((kt & 1) * ATT_STAGE_H) * 2 + lOff;
        const uint32_t vAddr = kAddr + (uint32_t)ATT_TILE_H * 2;

        // S = Q @ K^T
        float s[2][8][4];
        #pragma unroll
        for (int mt = 0; mt < 2; mt++)
            #pragma unroll
            for (int nt = 0; nt < 8; nt++)
                #pragma unroll
                for (int e = 0; e < 4; e++) s[mt][nt][e] = 0.f;

        #pragma unroll
        for (int kk = 0; kk < 4; kk++) {
            uint32_t bq[4][4];
            #pragma unroll
            for (int np = 0; np < 4; np++)
                ldsm4(bq[np][0], bq[np][1], bq[np][2], bq[np][3],
                      kAddr + (uint32_t)(np * 16 * 72 + kk * 16) * 2);
            #pragma unroll
            for (int nt = 0; nt < 8; nt++) {
                uint32_t b0 = bq[nt >> 1][(nt & 1) * 2];
                uint32_t b1 = bq[nt >> 1][(nt & 1) * 2 + 1];
                #pragma unroll
                for (int mt = 0; mt < 2; mt++)
                    mma16(s[mt][nt][0], s[mt][nt][1], s[mt][nt][2], s[mt][nt][3],
                          qf[kk][mt][0], qf[kk][mt][1], qf[kk][mt][2], qf[kk][mt][3],
                          b0, b1);
            }
        }

        // causal mask
        if (kt >= 2 * qt) {
            int colbase = kt * 64;
            #pragma unroll
            for (int mt = 0; mt < 2; mt++) {
                int row = qt * 128 + m0 + mt * 16 + g;
                #pragma unroll
                for (int nt = 0; nt < 8; nt++) {
                    int col = colbase + nt * 8 + 2 * tg;
                    if (col > row)         s[mt][nt][0] = -1e30f;
                    if (col + 1 > row)     s[mt][nt][1] = -1e30f;
                    if (col > row + 8)     s[mt][nt][2] = -1e30f;
                    if (col + 1 > row + 8) s[mt][nt][3] = -1e30f;
                }
            }
        }

        // online softmax
        uint32_t p2[2][8][2];
        #pragma unroll
        for (int mt = 0; mt < 2; mt++) {
            float vm0 = -1e30f, vm1 = -1e30f;
            #pragma unroll
            for (int nt = 0; nt < 8; nt++) {
                vm0 = fmaxf(vm0, fmaxf(s[mt][nt][0], s[mt][nt][1]));
                vm1 = fmaxf(vm1, fmaxf(s[mt][nt][2], s[mt][nt][3]));
            }
            vm0 = fmaxf(vm0, __shfl_xor_sync(0xffffffffu, vm0, 1));
            vm0 = fmaxf(vm0, __shfl_xor_sync(0xffffffffu, vm0, 2));
            vm1 = fmaxf(vm1, __shfl_xor_sync(0xffffffffu, vm1, 1));
            vm1 = fmaxf(vm1, __shfl_xor_sync(0xffffffffu, vm1, 2));
            int i0 = mt * 2, i1 = mt * 2 + 1;
            float mn0 = fmaxf(mrow[i0], vm0), mn1 = fmaxf(mrow[i1], vm1);
            float c0 = __expf(mrow[i0] - mn0), c1 = __expf(mrow[i1] - mn1);
            mrow[i0] = mn0; mrow[i1] = mn1;
            float sum0 = 0.f, sum1 = 0.f;
            #pragma unroll
            for (int nt = 0; nt < 8; nt++) {
                float e0 = __expf(s[mt][nt][0] - mn0);
                float e1 = __expf(s[mt][nt][1] - mn0);
                float e2 = __expf(s[mt][nt][2] - mn1);
                float e3 = __expf(s[mt][nt][3] - mn1);
                sum0 += e0 + e1; sum1 += e2 + e3;
                p2[mt][nt][0] = packh2(e0, e1);
                p2[mt][nt][1] = packh2(e2, e3);
            }
            sum0 += __shfl_xor_sync(0xffffffffu, sum0, 1);
            sum0 += __shfl_xor_sync(0xffffffffu, sum0, 2);
            sum1 += __shfl_xor_sync(0xffffffffu, sum1, 1);
            sum1 += __shfl_xor_sync(0xffffffffu, sum1, 2);
            lrow[i0] = lrow[i0] * c0 + sum0;
            lrow[i1] = lrow[i1] * c1 + sum1;
            #pragma unroll
            for (int nt = 0; nt < 8; nt++) {
                o[mt][nt][0] *= c0; o[mt][nt][1] *= c0;
                o[mt][nt][2] *= c1; o[mt][nt][3] *= c1;
            }
        }

        // O += P @ V
        #pragma unroll
        for (int kk = 0; kk < 4; kk++) {
            int nt0 = kk * 2;
            uint32_t bq[4][4];
            #pragma unroll
            for (int np = 0; np < 4; np++)
                ldsm4(bq[np][0], bq[np][1], bq[np][2], bq[np][3],
                      vAddr + (uint32_t)(np * 16 * 72 + kk * 16) * 2);
            #pragma unroll
            for (int nt = 0; nt < 8; nt++) {
                uint32_t b0 = bq[nt >> 1][(nt & 1) * 2];
                uint32_t b1 = bq[nt >> 1][(nt & 1) * 2 + 1];
                #pragma unroll
                for (int mt = 0; mt < 2; mt++)
                    mma16(o[mt][nt][0], o[mt][nt][1], o[mt][nt][2], o[mt][nt][3],
                          p2[mt][nt0][0], p2[mt][nt0][1],
                          p2[mt][nt0 + 1][0], p2[mt][nt0 + 1][1],
                          b0, b1);
            }
        }
    }

    // epilogue: normalize, write fp16 [bt][h*64+d]
    #pragma unroll
    for (int mt = 0; mt < 2; mt++) {
        int r = m0 + mt * 16 + g;
        int grow = qt * 128 + r;
        float inv0 = 1.f / lrow[mt * 2];
        float inv1 = 1.f / lrow[mt * 2 + 1];
        #pragma unroll
        for (int nt = 0; nt < 8; nt++) {
            int c = h * 64 + nt * 8 + 2 * tg;
            size_t base0 = ((size_t)(b * kT) + grow) * kD + c;
            size_t base1 = ((size_t)(b * kT) + grow + 8) * kD + c;
            *(uint32_t*)&g_atth[base0] = packh2(o[mt][nt][0] * inv0, o[mt][nt][1] * inv0);
            *(uint32_t*)&g_atth[base1] = packh2(o[mt][nt][2] * inv1, o[mt][nt][3] * inv1);
        }
    }
}

// ---------------------------------------------------------------------------
extern "C" void kernel_launch(void* const* d_in, const int* in_sizes, int n_in,
                              void* d_out, int out_size)
{
    const float* x    = (const float*)d_in[0];
    const float* Wqkv = (const float*)d_in[1];
    const float* Wout = (const float*)d_in[2];
    float* out        = (float*)d_out;

    static bool attr_set = false;
    if (!attr_set) {
        cudaFuncSetAttribute(gemm_h_kernel,
                             cudaFuncAttributeMaxDynamicSharedMemorySize, GH_SMEM_BYTES);
        cudaFuncSetAttribute(attn_h_kernel,
                             cudaFuncAttributeMaxDynamicSharedMemorySize, ATT_SMEM_BYTES);
        attr_set = true;
    }

    __half* d_xh;    cudaGetSymbolAddress((void**)&d_xh, g_xh);
    __half* d_wqkvt; cudaGetSymbolAddress((void**)&d_wqkvt, g_wqkvt);
    __half* d_woutt; cudaGetSymbolAddress((void**)&d_woutt, g_woutt);
    __half* d_atth;  cudaGetSymbolAddress((void**)&d_atth, g_atth);
    float*  d_qkv;   cudaGetSymbolAddress((void**)&d_qkv, g_qkv);

    dim3 blk(256);

    // 0) convert inputs
    int nx = kBT * kD / 4;
    round_half_kernel<<<(nx + 255) / 256, blk>>>(x, (__half2*)d_xh, nx);
    round_transpose_kernel<<<dim3(kQKVN / 32, kD / 32), blk>>>(Wqkv, d_wqkvt, kD, kQKVN);
    round_transpose_kernel<<<dim3(kD / 32, kD / 32), blk>>>(Wout, d_woutt, kD, kD);

    // 1) QKV projection (fp16 mma + ldmatrix, BK=64)
    gemm_h_kernel<<<dim3(kQKVN / 128, kBT / 128), blk, GH_SMEM_BYTES>>>(
        d_xh, d_wqkvt, d_qkv, kBT, kQKVN, kD);

    // 2) RoPE + head split (fp16 out, Q pre-scaled)
    int rope_threads = kBT * kH * 32;
    rope_kernel<<<(rope_threads + 255) / 256, blk>>>();

    // 2b) V transpose
    vtrans_kernel<<<dim3(kT / 64, kB * kH), blk>>>();

    // 3) causal flash attention (fp16 mma, register Q/P, ldmatrix K/V)
    attn_h_kernel<<<dim3(kT / 128, kB * kH), dim3(128), ATT_SMEM_BYTES>>>();

    // 4) output projection (fp16 mma + ldmatrix, BK=64)
    gemm_h_kernel<<<dim3(kD / 128, kBT / 128), blk, GH_SMEM_BYTES>>>(
        d_atth, d_woutt, out, kBT, kD, kD);
}